// round 6
// baseline (speedup 1.0000x reference)
#include <cuda_runtime.h>

// Problem constants (fixed by setup_inputs): B=4, C=128, W=H=64
#define NB  4
#define NCH 64      // c_half = c_out
#define ND  8       // d_qk
#define NN  4096    // W*H tokens
#define MT  64      // query tile (rows per block)  -> grid 256
#define NT  64      // key tile
#define VPAD 68     // padded smem row stride for v (floats)
#define WPAD 68     // padded smem row stride for w (floats)

typedef unsigned long long ull;

// Scratch (no cudaMalloc allowed) — 16B aligned for vector access.
__device__ __align__(16) float g_p2t[NB * NN * ND];    // [b][n][8]
__device__ __align__(16) float g_p3t[NB * NN * ND];    // [b][n][8]
__device__ __align__(16) float g_v3t[NB * NN * NCH];   // [b][n][64]

// ---- packed fp32x2 helpers (PTX only; ptxas won't auto-fuse) ----
__device__ __forceinline__ ull f2fma(ull a, ull b, ull c) {
    ull d; asm("fma.rn.f32x2 %0, %1, %2, %3;" : "=l"(d) : "l"(a), "l"(b), "l"(c)); return d;
}
__device__ __forceinline__ ull f2mul(ull a, ull b) {
    ull d; asm("mul.rn.f32x2 %0, %1, %2;" : "=l"(d) : "l"(a), "l"(b)); return d;
}
__device__ __forceinline__ ull fpack(float x) {
    ull d; asm("mov.b64 %0, {%1, %1};" : "=l"(d) : "f"(x)); return d;
}
__device__ __forceinline__ float2 funpack(ull a) {
    float2 r; asm("mov.b64 {%0, %1}, %2;" : "=f"(r.x), "=f"(r.y) : "l"(a)); return r;
}

// dot of 8-float q (packed as 4 x f32x2) with an 8-float key (two 16B words)
__device__ __forceinline__ float dotp8(const ull* q, ulonglong2 kA, ulonglong2 kB) {
    ull a = f2mul(q[0], kA.x);
    a = f2fma(q[1], kA.y, a);
    a = f2fma(q[2], kB.x, a);
    a = f2fma(q[3], kB.y, a);
    float2 f = funpack(a);
    return f.x + f.y;
}

// ---------------------------------------------------------------------------
// K1: 1x1-conv projections, written n-major. 128 threads, 128 blocks.
// ---------------------------------------------------------------------------
__global__ void proj_kernel(const float* __restrict__ x,
                            const float* __restrict__ wq2, const float* __restrict__ bq2,
                            const float* __restrict__ wq3, const float* __restrict__ bq3,
                            const float* __restrict__ wv3, const float* __restrict__ bv3)
{
    __shared__ float s_wq2[ND * NCH];
    __shared__ float s_wq3[ND * NCH];
    __shared__ float s_wv3[NCH * NCH];
    __shared__ float s_b[2 * ND + NCH];

    const int tid = threadIdx.x;
    for (int i = tid; i < ND * NCH; i += 128) { s_wq2[i] = wq2[i]; s_wq3[i] = wq3[i]; }
    for (int i = tid; i < NCH * NCH; i += 128) s_wv3[i] = wv3[i];
    if (tid < ND)                s_b[tid] = bq2[tid];
    else if (tid < 2 * ND)       s_b[tid] = bq3[tid - ND];
    else if (tid < 2 * ND + NCH) s_b[tid] = bv3[tid - 2 * ND];
    __syncthreads();

    const int b = blockIdx.y;
    const int n = blockIdx.x * 128 + tid;
    const float* xb = x + (size_t)b * (2 * NCH) * NN;

    float p2[ND], p3[ND], v[NCH];
#pragma unroll
    for (int d = 0; d < ND; d++) { p2[d] = s_b[d]; p3[d] = s_b[ND + d]; }
#pragma unroll
    for (int c = 0; c < NCH; c++) v[c] = s_b[2 * ND + c];

    for (int c = 0; c < NCH; c++) {
        const float x3v = xb[c * NN + n];
        const float x2v = xb[(NCH + c) * NN + n];
#pragma unroll
        for (int d = 0; d < ND; d++) {
            p2[d] = fmaf(s_wq2[d * NCH + c], x2v, p2[d]);
            p3[d] = fmaf(s_wq3[d * NCH + c], x3v, p3[d]);
        }
#pragma unroll
        for (int o = 0; o < NCH; o++)
            v[o] = fmaf(s_wv3[o * NCH + c], x3v, v[o]);
    }

    float* o2 = g_p2t + ((size_t)b * NN + n) * ND;
    float* o3 = g_p3t + ((size_t)b * NN + n) * ND;
    float* ov = g_v3t + ((size_t)b * NN + n) * NCH;
#pragma unroll
    for (int d = 0; d < ND; d++) { o2[d] = p2[d]; o3[d] = p3[d]; }
#pragma unroll
    for (int c = 0; c < NCH; c++) ov[c] = v[c];
}

// ---------------------------------------------------------------------------
// K2: two-phase attention per (batch, 64-query tile). 256 threads.
//  Score/weight roles: mq = tid&15 (4 query rows m=mq*4+k),
//                      np = tid>>4 (keys n = i*16+np, i=0..3)
//  GEMM roles: kq = tid>>6 (16 keys), r=tid&63: mgq=r&3 (16 m's), cgq=r>>2
//              (4 c's); 16m x 4c accumulator as 8x4 f32x2 pairs.
// ---------------------------------------------------------------------------
__global__ __launch_bounds__(256, 2) void att_kernel(const float* __restrict__ x,
                                                     const float* __restrict__ g2p,
                                                     const float* __restrict__ g3p,
                                                     float* __restrict__ out)
{
    __shared__ __align__(16) float s_p2[2][NT * ND];     // double-buffered [n][8]
    __shared__ __align__(16) float s_p3[2][NT * ND];
    __shared__ __align__(16) float s_v[NT][VPAD];        // [n][c]
    __shared__ __align__(16) float s_w[NT][WPAD];        // [n][m]
    __shared__ __align__(16) ull   s_q[MT * 4];          // packed q rows
    __shared__ __align__(16) float s_sc32[MT];
    __shared__ __align__(16) float s_sc33[MT];

    const int tid = threadIdx.x;
    const int b   = blockIdx.y;
    const int m0  = blockIdx.x * MT;
    const int mq  = tid & 15;
    const int np  = tid >> 4;

    const float g2 = *g2p;
    const float g3 = *g3p;

    const float4* p2g = (const float4*)g_p2t + (size_t)b * NN * 2;
    const float4* p3g = (const float4*)g_p3t + (size_t)b * NN * 2;

    // pack 4 query rows (p3) as f32x2 pairs
    ull qp[4][4];
#pragma unroll
    for (int k = 0; k < 4; k++) {
        const ulonglong2* qg =
            (const ulonglong2*)(g_p3t + ((size_t)b * NN + m0 + mq * 4 + k) * ND);
        ulonglong2 u0 = qg[0], u1 = qg[1];
        qp[k][0] = u0.x; qp[k][1] = u0.y; qp[k][2] = u1.x; qp[k][3] = u1.y;
    }

    // ---------------- Phase 1: softmax denominators (max-free) ----------------
    float sum32[4] = {0.f, 0.f, 0.f, 0.f};
    float sum33[4] = {0.f, 0.f, 0.f, 0.f};
    float4 pr = (tid < 128) ? p2g[tid] : p3g[tid - 128];
    if (tid < 128) ((float4*)s_p2[0])[tid]       = pr;
    else           ((float4*)s_p3[0])[tid - 128] = pr;
    __syncthreads();
    for (int t = 0; t < NN / NT; t++) {
        const int cur = t & 1;
        if (t + 1 < NN / NT) {
            const int base = (t + 1) * NT * 2;
            pr = (tid < 128) ? p2g[base + tid] : p3g[base + tid - 128];
        }
#pragma unroll
        for (int i = 0; i < 4; i++) {
            const int n = i * 16 + np;
            const ulonglong2* r2 = (const ulonglong2*)(s_p2[cur] + n * ND);
            const ulonglong2* r3 = (const ulonglong2*)(s_p3[cur] + n * ND);
            const ulonglong2 k2A = r2[0], k2B = r2[1];
            const ulonglong2 k3A = r3[0], k3B = r3[1];
#pragma unroll
            for (int k = 0; k < 4; k++) {
                sum32[k] += __expf(dotp8(qp[k], k2A, k2B));
                sum33[k] += __expf(dotp8(qp[k], k3A, k3B));
            }
        }
        if (t + 1 < NN / NT) {
            if (tid < 128) ((float4*)s_p2[cur ^ 1])[tid]       = pr;
            else           ((float4*)s_p3[cur ^ 1])[tid - 128] = pr;
        }
        __syncthreads();
    }
    // lanes l / l+16 share mq
#pragma unroll
    for (int k = 0; k < 4; k++) {
        sum32[k] += __shfl_xor_sync(0xffffffffu, sum32[k], 16);
        sum33[k] += __shfl_xor_sync(0xffffffffu, sum33[k], 16);
    }
    // cross-warp reduction through smem (stage in s_w)
    {
        float* s_red = &s_w[0][0];
        const int warp = tid >> 5, lane = tid & 31;
        if (lane < 16) {
#pragma unroll
            for (int k = 0; k < 4; k++) {
                s_red[(lane * 8 + warp) * 8 + k]     = sum32[k];
                s_red[(lane * 8 + warp) * 8 + 4 + k] = sum33[k];
            }
        }
        __syncthreads();
        if (tid < 128) {
            const int m = tid >> 1, type = tid & 1;
            const int mq_ = m >> 2, k_ = m & 3;
            float s = 0.f;
#pragma unroll
            for (int w = 0; w < 8; w++)
                s += s_red[(mq_ * 8 + w) * 8 + type * 4 + k_];
            if (type == 0) s_sc32[m] = g2 / s;
            else           s_sc33[m] = g3 / s;
        }
    }
    // stash packed q rows for phase 2 (frees registers)
    if (np == 0) {
#pragma unroll
        for (int k = 0; k < 4; k++) {
            ulonglong2* d = (ulonglong2*)(s_q + (size_t)(mq * 4 + k) * 4);
            ulonglong2 a, c;
            a.x = qp[k][0]; a.y = qp[k][1];
            c.x = qp[k][2]; c.y = qp[k][3];
            d[0] = a; d[1] = c;
        }
    }

    // ---------------- Phase 2: combined-weight GEMM ----------------
    const float4* vg = (const float4*)g_v3t + (size_t)b * NN * (NCH / 4);
    const int kq  = tid >> 6;
    const int r63 = tid & 63;
    const int mgq = r63 & 3;                 // 16 m's = mgq*16 ..
    const int cgq = r63 >> 2;                // 4 c's  = cgq*4 ..

    ull acc[8][4];
#pragma unroll
    for (int p = 0; p < 8; p++)
#pragma unroll
        for (int j = 0; j < 4; j++) acc[p][j] = 0ull;

    // preamble: p-tile0 to buf0, prefetch p-tile1 + v-tile0
    pr = (tid < 128) ? p2g[tid] : p3g[tid - 128];
    float4 vr[4];
#pragma unroll
    for (int k = 0; k < 4; k++) vr[k] = vg[tid + k * 256];
    if (tid < 128) ((float4*)s_p2[0])[tid]       = pr;
    else           ((float4*)s_p3[0])[tid - 128] = pr;
    pr = (tid < 128) ? p2g[NT * 2 + tid] : p3g[NT * 2 + tid - 128];
    __syncthreads();   // p_db[0], s_sc, s_q ready; s_w staging free

    for (int t = 0; t < NN / NT; t++) {
        const int cur = t & 1;
        // fill v(t) and p(t+1)  [prior gemm done via syncA; gen(t-1) read cur^1 before syncB]
#pragma unroll
        for (int k = 0; k < 4; k++) {
            const int fi = tid + k * 256;
            *(float4*)(&s_v[fi >> 4][(fi & 15) * 4]) = vr[k];
        }
        if (t + 1 < NN / NT) {
            if (tid < 128) ((float4*)s_p2[cur ^ 1])[tid]       = pr;
            else           ((float4*)s_p3[cur ^ 1])[tid - 128] = pr;
        }
        // gen w(t) from p_db[cur]
        {
            ull qr[4][4];
#pragma unroll
            for (int k = 0; k < 4; k++) {
                const ulonglong2* s = (const ulonglong2*)(s_q + (size_t)(mq * 4 + k) * 4);
                ulonglong2 u0 = s[0], u1 = s[1];
                qr[k][0] = u0.x; qr[k][1] = u0.y; qr[k][2] = u1.x; qr[k][3] = u1.y;
            }
            const float4 scA = *(const float4*)&s_sc32[mq * 4];
            const float4 scB = *(const float4*)&s_sc33[mq * 4];
            const float sA[4] = {scA.x, scA.y, scA.z, scA.w};
            const float sB[4] = {scB.x, scB.y, scB.z, scB.w};
#pragma unroll
            for (int i = 0; i < 4; i++) {
                const int n = i * 16 + np;
                const ulonglong2* r2 = (const ulonglong2*)(s_p2[cur] + n * ND);
                const ulonglong2* r3 = (const ulonglong2*)(s_p3[cur] + n * ND);
                const ulonglong2 k2A = r2[0], k2B = r2[1];
                const ulonglong2 k3A = r3[0], k3B = r3[1];
                float wv4[4];
#pragma unroll
                for (int k = 0; k < 4; k++) {
                    const float e32 = __expf(dotp8(qr[k], k2A, k2B));
                    const float e33 = __expf(dotp8(qr[k], k3A, k3B));
                    wv4[k] = fmaf(sA[k], e32, sB[k] * e33);
                }
                float4 wv; wv.x = wv4[0]; wv.y = wv4[1]; wv.z = wv4[2]; wv.w = wv4[3];
                *(float4*)(&s_w[n][mq * 4]) = wv;
            }
        }
        // prefetch next tiles (lands during gemm)
        if (t + 1 < NN / NT) {
#pragma unroll
            for (int k = 0; k < 4; k++) vr[k] = vg[(t + 1) * NT * 16 + tid + k * 256];
        }
        if (t + 2 < NN / NT) {
            const int base = (t + 2) * NT * 2;
            pr = (tid < 128) ? p2g[base + tid] : p3g[base + tid - 128];
        }
        __syncthreads();   // B: w(t), v(t) visible

        // gemm: acc[m][c] += w[n][m] * v[n][c] over this thread's 16 keys
#pragma unroll 8
        for (int nn = 0; nn < 16; nn++) {
            const int n = kq * 16 + nn;
            const ulonglong2* wrow = (const ulonglong2*)(&s_w[n][mgq * 16]);
            const ulonglong2 wA = wrow[0], wB = wrow[1];
            const ulonglong2 wC = wrow[2], wD = wrow[3];
            const float4 vv = *(const float4*)(&s_v[n][cgq * 4]);
            const ull v0 = fpack(vv.x), v1 = fpack(vv.y);
            const ull v2 = fpack(vv.z), v3 = fpack(vv.w);
            acc[0][0] = f2fma(wA.x, v0, acc[0][0]);
            acc[0][1] = f2fma(wA.x, v1, acc[0][1]);
            acc[0][2] = f2fma(wA.x, v2, acc[0][2]);
            acc[0][3] = f2fma(wA.x, v3, acc[0][3]);
            acc[1][0] = f2fma(wA.y, v0, acc[1][0]);
            acc[1][1] = f2fma(wA.y, v1, acc[1][1]);
            acc[1][2] = f2fma(wA.y, v2, acc[1][2]);
            acc[1][3] = f2fma(wA.y, v3, acc[1][3]);
            acc[2][0] = f2fma(wB.x, v0, acc[2][0]);
            acc[2][1] = f2fma(wB.x, v1, acc[2][1]);
            acc[2][2] = f2fma(wB.x, v2, acc[2][2]);
            acc[2][3] = f2fma(wB.x, v3, acc[2][3]);
            acc[3][0] = f2fma(wB.y, v0, acc[3][0]);
            acc[3][1] = f2fma(wB.y, v1, acc[3][1]);
            acc[3][2] = f2fma(wB.y, v2, acc[3][2]);
            acc[3][3] = f2fma(wB.y, v3, acc[3][3]);
            acc[4][0] = f2fma(wC.x, v0, acc[4][0]);
            acc[4][1] = f2fma(wC.x, v1, acc[4][1]);
            acc[4][2] = f2fma(wC.x, v2, acc[4][2]);
            acc[4][3] = f2fma(wC.x, v3, acc[4][3]);
            acc[5][0] = f2fma(wC.y, v0, acc[5][0]);
            acc[5][1] = f2fma(wC.y, v1, acc[5][1]);
            acc[5][2] = f2fma(wC.y, v2, acc[5][2]);
            acc[5][3] = f2fma(wC.y, v3, acc[5][3]);
            acc[6][0] = f2fma(wD.x, v0, acc[6][0]);
            acc[6][1] = f2fma(wD.x, v1, acc[6][1]);
            acc[6][2] = f2fma(wD.x, v2, acc[6][2]);
            acc[6][3] = f2fma(wD.x, v3, acc[6][3]);
            acc[7][0] = f2fma(wD.y, v0, acc[7][0]);
            acc[7][1] = f2fma(wD.y, v1, acc[7][1]);
            acc[7][2] = f2fma(wD.y, v2, acc[7][2]);
            acc[7][3] = f2fma(wD.y, v3, acc[7][3]);
        }
        __syncthreads();   // A: gemm done; buffers reusable
    }

    // ---------------- cross-K reduction (4 partials) + epilogue ----------------
    float accf[16][4];
#pragma unroll
    for (int p = 0; p < 8; p++)
#pragma unroll
        for (int j = 0; j < 4; j++) {
            const float2 f = funpack(acc[p][j]);
            accf[2 * p][j]     = f.x;
            accf[2 * p + 1][j] = f.y;
        }
    float* red1 = &s_w[0][0];
    float* red2 = &s_v[0][0];

    if (kq == 2) {
#pragma unroll
        for (int rr = 0; rr < 16; rr++) {
            float4 o; o.x = accf[rr][0]; o.y = accf[rr][1]; o.z = accf[rr][2]; o.w = accf[rr][3];
            *(float4*)&red1[(mgq * 16 + rr) * WPAD + cgq * 4] = o;
        }
    } else if (kq == 3) {
#pragma unroll
        for (int rr = 0; rr < 16; rr++) {
            float4 o; o.x = accf[rr][0]; o.y = accf[rr][1]; o.z = accf[rr][2]; o.w = accf[rr][3];
            *(float4*)&red2[(mgq * 16 + rr) * VPAD + cgq * 4] = o;
        }
    }
    __syncthreads();
    if (kq == 0) {
#pragma unroll
        for (int rr = 0; rr < 16; rr++) {
            const float4 a = *(const float4*)&red1[(mgq * 16 + rr) * WPAD + cgq * 4];
            accf[rr][0] += a.x; accf[rr][1] += a.y; accf[rr][2] += a.z; accf[rr][3] += a.w;
        }
    } else if (kq == 1) {
#pragma unroll
        for (int rr = 0; rr < 16; rr++) {
            const float4 a = *(const float4*)&red2[(mgq * 16 + rr) * VPAD + cgq * 4];
            accf[rr][0] += a.x; accf[rr][1] += a.y; accf[rr][2] += a.z; accf[rr][3] += a.w;
        }
    }
    __syncthreads();
    if (kq == 1) {
#pragma unroll
        for (int rr = 0; rr < 16; rr++) {
            float4 o; o.x = accf[rr][0]; o.y = accf[rr][1]; o.z = accf[rr][2]; o.w = accf[rr][3];
            *(float4*)&red1[(mgq * 16 + rr) * WPAD + cgq * 4] = o;
        }
    }
    __syncthreads();
    if (kq == 0) {
        const float* xb = x + (size_t)b * (2 * NCH) * NN;   // x3 = channels 0..63
        float* ob = out + (size_t)b * NCH * NN;
#pragma unroll
        for (int rr = 0; rr < 16; rr++) {
            const float4 a = *(const float4*)&red1[(mgq * 16 + rr) * WPAD + cgq * 4];
            accf[rr][0] += a.x; accf[rr][1] += a.y; accf[rr][2] += a.z; accf[rr][3] += a.w;
        }
#pragma unroll
        for (int j = 0; j < 4; j++) {
            const int c = cgq * 4 + j;
#pragma unroll
            for (int blk = 0; blk < 4; blk++) {
                const int mm = m0 + mgq * 16 + blk * 4;
                const float4 xv = *(const float4*)(xb + (size_t)c * NN + mm);
                float4 o;
                o.x = accf[blk * 4 + 0][j] + xv.x;
                o.y = accf[blk * 4 + 1][j] + xv.y;
                o.z = accf[blk * 4 + 2][j] + xv.z;
                o.w = accf[blk * 4 + 3][j] + xv.w;
                *(float4*)(ob + (size_t)c * NN + mm) = o;
            }
        }
    }
}

extern "C" void kernel_launch(void* const* d_in, const int* in_sizes, int n_in,
                              void* d_out, int out_size)
{
    const float* x   = (const float*)d_in[0];
    const float* wq2 = (const float*)d_in[1];
    const float* bq2 = (const float*)d_in[2];
    const float* wq3 = (const float*)d_in[3];
    const float* bq3 = (const float*)d_in[4];
    const float* wv3 = (const float*)d_in[5];
    const float* bv3 = (const float*)d_in[6];
    const float* g2  = (const float*)d_in[7];
    const float* g3  = (const float*)d_in[8];
    float* out = (float*)d_out;

    proj_kernel<<<dim3(NN / 128, NB), 128>>>(x, wq2, bq2, wq3, bq3, wv3, bv3);
    att_kernel<<<dim3(NN / MT, NB), 256>>>(x, g2, g3, out);
}

// round 7
// speedup vs baseline: 1.5195x; 1.5195x over previous
#include <cuda_runtime.h>

// Problem constants (fixed by setup_inputs): B=4, C=128, W=H=64
#define NB  4
#define NCH 64      // c_half = c_out
#define ND  8       // d_qk
#define NN  4096    // W*H tokens
#define MT  64      // query tile (rows per block)  -> grid 256
#define NT  64      // key tile
#define VPAD 68     // padded smem row stride for v (floats)
#define WPAD 68     // padded smem row stride for w (floats)

// Scratch (no cudaMalloc allowed) — 16B aligned for vector access.
__device__ __align__(16) float g_p2t[NB * NN * ND];    // [b][n][8]
__device__ __align__(16) float g_p3t[NB * NN * ND];    // [b][n][8]
__device__ __align__(16) float g_v3t[NB * NN * NCH];   // [b][n][64]

// ---------------------------------------------------------------------------
// K1: 1x1-conv projections, written n-major. 128 threads, 128 blocks.
// ---------------------------------------------------------------------------
__global__ void proj_kernel(const float* __restrict__ x,
                            const float* __restrict__ wq2, const float* __restrict__ bq2,
                            const float* __restrict__ wq3, const float* __restrict__ bq3,
                            const float* __restrict__ wv3, const float* __restrict__ bv3)
{
    __shared__ float s_wq2[ND * NCH];
    __shared__ float s_wq3[ND * NCH];
    __shared__ float s_wv3[NCH * NCH];
    __shared__ float s_b[2 * ND + NCH];

    const int tid = threadIdx.x;
    for (int i = tid; i < ND * NCH; i += 128) { s_wq2[i] = wq2[i]; s_wq3[i] = wq3[i]; }
    for (int i = tid; i < NCH * NCH; i += 128) s_wv3[i] = wv3[i];
    if (tid < ND)                s_b[tid] = bq2[tid];
    else if (tid < 2 * ND)       s_b[tid] = bq3[tid - ND];
    else if (tid < 2 * ND + NCH) s_b[tid] = bv3[tid - 2 * ND];
    __syncthreads();

    const int b = blockIdx.y;
    const int n = blockIdx.x * 128 + tid;
    const float* xb = x + (size_t)b * (2 * NCH) * NN;

    float p2[ND], p3[ND], v[NCH];
#pragma unroll
    for (int d = 0; d < ND; d++) { p2[d] = s_b[d]; p3[d] = s_b[ND + d]; }
#pragma unroll
    for (int c = 0; c < NCH; c++) v[c] = s_b[2 * ND + c];

    for (int c = 0; c < NCH; c++) {
        const float x3v = xb[c * NN + n];
        const float x2v = xb[(NCH + c) * NN + n];
#pragma unroll
        for (int d = 0; d < ND; d++) {
            p2[d] = fmaf(s_wq2[d * NCH + c], x2v, p2[d]);
            p3[d] = fmaf(s_wq3[d * NCH + c], x3v, p3[d]);
        }
#pragma unroll
        for (int o = 0; o < NCH; o++)
            v[o] = fmaf(s_wv3[o * NCH + c], x3v, v[o]);
    }

    float* o2 = g_p2t + ((size_t)b * NN + n) * ND;
    float* o3 = g_p3t + ((size_t)b * NN + n) * ND;
    float* ov = g_v3t + ((size_t)b * NN + n) * NCH;
#pragma unroll
    for (int d = 0; d < ND; d++) { o2[d] = p2[d]; o3[d] = p3[d]; }
#pragma unroll
    for (int c = 0; c < NCH; c++) ov[c] = v[c];
}

__device__ __forceinline__ float dot8(const float4 a, const float4 b,
                                      const float4 c, const float4 d)
{
    float s = a.x * c.x;
    s = fmaf(a.y, c.y, s);
    s = fmaf(a.z, c.z, s);
    s = fmaf(a.w, c.w, s);
    s = fmaf(b.x, d.x, s);
    s = fmaf(b.y, d.y, s);
    s = fmaf(b.z, d.z, s);
    s = fmaf(b.w, d.w, s);
    return s;
}

// ---------------------------------------------------------------------------
// K2: two-phase attention per (batch, 64-query tile). 256 threads, 3 blk/SM.
//  Score/weight phases: mq = tid&15 -> 4 query rows m=mq*4+k
//                       np = tid>>4 -> keys n = i*16+np, i=0..3
//  GEMM: half = tid>>7 takes half of each key tile; within half:
//        mg = t7&7 (8 m's), cg = t7>>3 (4 c's); 8x4 fp32 register tile.
// ---------------------------------------------------------------------------
__global__ __launch_bounds__(256, 3) void att_kernel(const float* __restrict__ x,
                                                     const float* __restrict__ g2p,
                                                     const float* __restrict__ g3p,
                                                     float* __restrict__ out)
{
    __shared__ __align__(16) float s_p2[2][NT * ND];     // double-buffered [n][8]
    __shared__ __align__(16) float s_p3[2][NT * ND];
    __shared__ __align__(16) float s_v[NT][VPAD];        // [n][c]
    __shared__ __align__(16) float s_w[NT][WPAD];        // [n][m]
    __shared__ __align__(16) float s_q[MT * ND];         // stashed q rows
    __shared__ __align__(16) float s_sc32[MT];
    __shared__ __align__(16) float s_sc33[MT];

    const int tid = threadIdx.x;
    const int b   = blockIdx.y;
    const int m0  = blockIdx.x * MT;
    const int mq  = tid & 15;
    const int np  = tid >> 4;

    const float g2 = *g2p;
    const float g3 = *g3p;

    const float4* p2g = (const float4*)g_p2t + (size_t)b * NN * 2;
    const float4* p3g = (const float4*)g_p3t + (size_t)b * NN * 2;

    // 4 query rows (p3) in registers for phase 1
    float4 qa[4], qb[4];
#pragma unroll
    for (int k = 0; k < 4; k++) {
        qa[k] = p3g[(m0 + mq * 4 + k) * 2 + 0];
        qb[k] = p3g[(m0 + mq * 4 + k) * 2 + 1];
    }

    // ---------------- Phase 1: softmax denominators (max-free) ----------------
    float sum32[4] = {0.f, 0.f, 0.f, 0.f};
    float sum33[4] = {0.f, 0.f, 0.f, 0.f};
    float4 pr = (tid < 128) ? p2g[tid] : p3g[tid - 128];
    if (tid < 128) ((float4*)s_p2[0])[tid]       = pr;
    else           ((float4*)s_p3[0])[tid - 128] = pr;
    __syncthreads();
    for (int t = 0; t < NN / NT; t++) {
        const int cur = t & 1;
        if (t + 1 < NN / NT) {
            const int base = (t + 1) * NT * 2;
            pr = (tid < 128) ? p2g[base + tid] : p3g[base + tid - 128];
        }
#pragma unroll
        for (int i = 0; i < 4; i++) {
            const int n = i * 16 + np;
            const float4 k2a = ((const float4*)s_p2[cur])[n * 2];
            const float4 k2b = ((const float4*)s_p2[cur])[n * 2 + 1];
            const float4 k3a = ((const float4*)s_p3[cur])[n * 2];
            const float4 k3b = ((const float4*)s_p3[cur])[n * 2 + 1];
#pragma unroll
            for (int k = 0; k < 4; k++) {
                sum32[k] += __expf(dot8(qa[k], qb[k], k2a, k2b));
                sum33[k] += __expf(dot8(qa[k], qb[k], k3a, k3b));
            }
        }
        if (t + 1 < NN / NT) {
            if (tid < 128) ((float4*)s_p2[cur ^ 1])[tid]       = pr;
            else           ((float4*)s_p3[cur ^ 1])[tid - 128] = pr;
        }
        __syncthreads();
    }
    // lanes l / l+16 share mq
#pragma unroll
    for (int k = 0; k < 4; k++) {
        sum32[k] += __shfl_xor_sync(0xffffffffu, sum32[k], 16);
        sum33[k] += __shfl_xor_sync(0xffffffffu, sum33[k], 16);
    }
    // cross-warp reduction through smem (stage in s_w)
    {
        float* s_red = &s_w[0][0];
        const int warp = tid >> 5, lane = tid & 31;
        if (lane < 16) {
#pragma unroll
            for (int k = 0; k < 4; k++) {
                s_red[(lane * 8 + warp) * 8 + k]     = sum32[k];
                s_red[(lane * 8 + warp) * 8 + 4 + k] = sum33[k];
            }
        }
        __syncthreads();
        if (tid < 128) {
            const int m = tid >> 1, type = tid & 1;
            const int mq_ = m >> 2, k_ = m & 3;
            float s = 0.f;
#pragma unroll
            for (int w = 0; w < 8; w++)
                s += s_red[(mq_ * 8 + w) * 8 + type * 4 + k_];
            if (type == 0) s_sc32[m] = g2 / s;
            else           s_sc33[m] = g3 / s;
        }
    }
    // stash q rows to smem (frees 32 registers for phase 2)
    if (np == 0) {
#pragma unroll
        for (int k = 0; k < 4; k++) {
            float4* d = (float4*)(s_q + (size_t)(mq * 4 + k) * ND);
            d[0] = qa[k];
            d[1] = qb[k];
        }
    }

    // ---------------- Phase 2: combined-weight GEMM ----------------
    const float4* vg = (const float4*)g_v3t + (size_t)b * NN * (NCH / 4);
    const int half = tid >> 7;               // n-half of each 64-key tile
    const int t7   = tid & 127;
    const int mg   = t7 & 7;                 // 8 m's = mg*8 .. mg*8+7
    const int cg   = t7 >> 3;                // 4 c's = cg*4 .. cg*4+3
    const int nlo  = half * 32;

    float acc[8][4];
#pragma unroll
    for (int r = 0; r < 8; r++)
#pragma unroll
        for (int j = 0; j < 4; j++) acc[r][j] = 0.f;

    // preamble: p-tile0 -> buf0, prefetch p-tile1 + v-tile0
    pr = (tid < 128) ? p2g[tid] : p3g[tid - 128];
    float4 vr[4];
#pragma unroll
    for (int k = 0; k < 4; k++) vr[k] = vg[tid + k * 256];
    if (tid < 128) ((float4*)s_p2[0])[tid]       = pr;
    else           ((float4*)s_p3[0])[tid - 128] = pr;
    pr = (tid < 128) ? p2g[NT * 2 + tid] : p3g[NT * 2 + tid - 128];
    __syncthreads();   // p buf0, s_sc, s_q ready; s_w staging free

    for (int t = 0; t < NN / NT; t++) {
        const int cur = t & 1;
        // fill v(t), stage p(t+1)  [gemm(t-1) done at sync A]
#pragma unroll
        for (int k = 0; k < 4; k++) {
            const int fi = tid + k * 256;
            *(float4*)(&s_v[fi >> 4][(fi & 15) * 4]) = vr[k];
        }
        if (t + 1 < NN / NT) {
            if (tid < 128) ((float4*)s_p2[cur ^ 1])[tid]       = pr;
            else           ((float4*)s_p3[cur ^ 1])[tid - 128] = pr;
        }

        // weight gen for tile t, two query-row pairs at a time (low reg pressure)
#pragma unroll
        for (int kh = 0; kh < 2; kh++) {
            const int mrow = mq * 4 + kh * 2;
            const float4 q0a = ((const float4*)(s_q + (size_t)mrow * ND))[0];
            const float4 q0b = ((const float4*)(s_q + (size_t)mrow * ND))[1];
            const float4 q1a = ((const float4*)(s_q + (size_t)(mrow + 1) * ND))[0];
            const float4 q1b = ((const float4*)(s_q + (size_t)(mrow + 1) * ND))[1];
            const float2 sA = *(const float2*)&s_sc32[mrow];
            const float2 sB = *(const float2*)&s_sc33[mrow];
#pragma unroll
            for (int i = 0; i < 4; i++) {
                const int n = i * 16 + np;
                const float4 k2a = ((const float4*)s_p2[cur])[n * 2];
                const float4 k2b = ((const float4*)s_p2[cur])[n * 2 + 1];
                const float4 k3a = ((const float4*)s_p3[cur])[n * 2];
                const float4 k3b = ((const float4*)s_p3[cur])[n * 2 + 1];
                float2 wv;
                wv.x = fmaf(sA.x, __expf(dot8(q0a, q0b, k2a, k2b)),
                            sB.x * __expf(dot8(q0a, q0b, k3a, k3b)));
                wv.y = fmaf(sA.y, __expf(dot8(q1a, q1b, k2a, k2b)),
                            sB.y * __expf(dot8(q1a, q1b, k3a, k3b)));
                *(float2*)(&s_w[n][mrow]) = wv;
            }
        }

        // prefetch next tiles (lands during gemm)
        if (t + 1 < NN / NT) {
#pragma unroll
            for (int k = 0; k < 4; k++) vr[k] = vg[(t + 1) * NT * 16 + tid + k * 256];
        }
        if (t + 2 < NN / NT) {
            const int base = (t + 2) * NT * 2;
            pr = (tid < 128) ? p2g[base + tid] : p3g[base + tid - 128];
        }
        __syncthreads();   // B: w(t), v(t) visible

        // gemm: acc[m][c] += w[n][m] * v[n][c] over this thread's n-half
#pragma unroll 8
        for (int nn = 0; nn < 32; nn++) {
            const int n = nlo + nn;
            const float4 w0 = *(const float4*)(&s_w[n][mg * 8]);
            const float4 w1 = *(const float4*)(&s_w[n][mg * 8 + 4]);
            const float4 vv = *(const float4*)(&s_v[n][cg * 4]);
            acc[0][0] = fmaf(w0.x, vv.x, acc[0][0]);
            acc[0][1] = fmaf(w0.x, vv.y, acc[0][1]);
            acc[0][2] = fmaf(w0.x, vv.z, acc[0][2]);
            acc[0][3] = fmaf(w0.x, vv.w, acc[0][3]);
            acc[1][0] = fmaf(w0.y, vv.x, acc[1][0]);
            acc[1][1] = fmaf(w0.y, vv.y, acc[1][1]);
            acc[1][2] = fmaf(w0.y, vv.z, acc[1][2]);
            acc[1][3] = fmaf(w0.y, vv.w, acc[1][3]);
            acc[2][0] = fmaf(w0.z, vv.x, acc[2][0]);
            acc[2][1] = fmaf(w0.z, vv.y, acc[2][1]);
            acc[2][2] = fmaf(w0.z, vv.z, acc[2][2]);
            acc[2][3] = fmaf(w0.z, vv.w, acc[2][3]);
            acc[3][0] = fmaf(w0.w, vv.x, acc[3][0]);
            acc[3][1] = fmaf(w0.w, vv.y, acc[3][1]);
            acc[3][2] = fmaf(w0.w, vv.z, acc[3][2]);
            acc[3][3] = fmaf(w0.w, vv.w, acc[3][3]);
            acc[4][0] = fmaf(w1.x, vv.x, acc[4][0]);
            acc[4][1] = fmaf(w1.x, vv.y, acc[4][1]);
            acc[4][2] = fmaf(w1.x, vv.z, acc[4][2]);
            acc[4][3] = fmaf(w1.x, vv.w, acc[4][3]);
            acc[5][0] = fmaf(w1.y, vv.x, acc[5][0]);
            acc[5][1] = fmaf(w1.y, vv.y, acc[5][1]);
            acc[5][2] = fmaf(w1.y, vv.z, acc[5][2]);
            acc[5][3] = fmaf(w1.y, vv.w, acc[5][3]);
            acc[6][0] = fmaf(w1.z, vv.x, acc[6][0]);
            acc[6][1] = fmaf(w1.z, vv.y, acc[6][1]);
            acc[6][2] = fmaf(w1.z, vv.z, acc[6][2]);
            acc[6][3] = fmaf(w1.z, vv.w, acc[6][3]);
            acc[7][0] = fmaf(w1.w, vv.x, acc[7][0]);
            acc[7][1] = fmaf(w1.w, vv.y, acc[7][1]);
            acc[7][2] = fmaf(w1.w, vv.z, acc[7][2]);
            acc[7][3] = fmaf(w1.w, vv.w, acc[7][3]);
        }
        __syncthreads();   // A: gemm done; buffers reusable
    }

    // ---------------- cross-half reduction + epilogue ----------------
    float* s_red = &s_v[0][0];               // reuse as [64 m][65]
    __syncthreads();
    if (half == 1) {
#pragma unroll
        for (int r = 0; r < 8; r++)
#pragma unroll
            for (int j = 0; j < 4; j++)
                s_red[(mg * 8 + r) * 65 + cg * 4 + j] = acc[r][j];
    }
    __syncthreads();
    if (half == 0) {
        const float* xb = x + (size_t)b * (2 * NCH) * NN;  // x3 = channels 0..63
        float* ob = out + (size_t)b * NCH * NN;
#pragma unroll
        for (int j = 0; j < 4; j++) {
            const int c = cg * 4 + j;
#pragma unroll
            for (int rb = 0; rb < 2; rb++) {
                const int mm = m0 + mg * 8 + rb * 4;
                const float4 xv = *(const float4*)(xb + (size_t)c * NN + mm);
                float4 o;
                o.x = acc[rb * 4 + 0][j] + s_red[(mg * 8 + rb * 4 + 0) * 65 + c] + xv.x;
                o.y = acc[rb * 4 + 1][j] + s_red[(mg * 8 + rb * 4 + 1) * 65 + c] + xv.y;
                o.z = acc[rb * 4 + 2][j] + s_red[(mg * 8 + rb * 4 + 2) * 65 + c] + xv.z;
                o.w = acc[rb * 4 + 3][j] + s_red[(mg * 8 + rb * 4 + 3) * 65 + c] + xv.w;
                *(float4*)(ob + (size_t)c * NN + mm) = o;
            }
        }
    }
}

extern "C" void kernel_launch(void* const* d_in, const int* in_sizes, int n_in,
                              void* d_out, int out_size)
{
    const float* x   = (const float*)d_in[0];
    const float* wq2 = (const float*)d_in[1];
    const float* bq2 = (const float*)d_in[2];
    const float* wq3 = (const float*)d_in[3];
    const float* bq3 = (const float*)d_in[4];
    const float* wv3 = (const float*)d_in[5];
    const float* bv3 = (const float*)d_in[6];
    const float* g2  = (const float*)d_in[7];
    const float* g3  = (const float*)d_in[8];
    float* out = (float*)d_out;

    proj_kernel<<<dim3(NN / 128, NB), 128>>>(x, wq2, bq2, wq3, bq3, wv3, bv3);
    att_kernel<<<dim3(NN / MT, NB), 256>>>(x, g2, g3, out);
}